// round 3
// baseline (speedup 1.0000x reference)
#include <cuda_runtime.h>
#include <cuda_bf16.h>

// EdgeScoringMLP: out[e] = MLP(concat(node[i[e]], node[j[e]], attr[e]))
// H=128, IN=258, H2=64. fp32 throughout, packed f32x2 FMA (Blackwell).
//
// Inputs (metadata order):
// 0 node_embed   [N,128]  f32
// 1 edge_index   [2,E]    int32  (harness materializes int64 as int32!)
// 2 edge_attr    [E,2]    f32
// 3 W1 [258,128] 4 b1[128] 5 ln_gamma[128] 6 ln_beta[128]
// 7 W2 [128,64]  8 b2[64]  9 W3[64,1] 10 b3[1]
// out: [E] f32

typedef unsigned long long ull;

__device__ __forceinline__ ull pack2(float a, float b) {
    ull r; asm("mov.b64 %0, {%1, %2};" : "=l"(r) : "f"(a), "f"(b)); return r;
}
__device__ __forceinline__ float2 unpack2(ull v) {
    float2 r; asm("mov.b64 {%0, %1}, %2;" : "=f"(r.x), "=f"(r.y) : "l"(v)); return r;
}
__device__ __forceinline__ ull ffma2(ull a, ull b, ull c) {
    ull d; asm("fma.rn.f32x2 %0, %1, %2, %3;" : "=l"(d) : "l"(a), "l"(b), "l"(c)); return d;
}
__device__ __forceinline__ ull add2(ull a, ull b) {
    ull d; asm("add.rn.f32x2 %0, %1, %2;" : "=l"(d) : "l"(a), "l"(b)); return d;
}
__device__ __forceinline__ ull mul2(ull a, ull b) {
    ull d; asm("mul.rn.f32x2 %0, %1, %2;" : "=l"(d) : "l"(a), "l"(b)); return d;
}

static constexpr int H     = 128;
static constexpr int IN    = 2 * H + 2;   // 258
static constexpr int H2    = 64;
static constexpr int TE    = 32;          // edges per CTA tile
static constexpr int H1PAD = 34;          // h1s row stride (2-way conflict max)

__global__ void __launch_bounds__(256)
edge_mlp_kernel(const float* __restrict__ node,
                const int* __restrict__ eidx,
                const float* __restrict__ attr,
                const float* __restrict__ W1,
                const float* __restrict__ b1,
                const float* __restrict__ ln_g,
                const float* __restrict__ ln_b,
                const float* __restrict__ W2,
                const float* __restrict__ b2,
                const float* __restrict__ W3,
                const float* __restrict__ b3,
                float* __restrict__ out,
                long long E)
{
    __shared__ __align__(16) float xs[IN * TE];       // 33024 B; reused as h1s after layer 1
    __shared__ ull psum[8][8], psq[8][8];             // per-warp LN partials (f32x2 pairs)
    __shared__ float mu_s[TE], rs_s[TE];
    __shared__ ull l3p[8][4];                         // layer-3 per-warp partials

    const int tid  = threadIdx.x;
    const int w    = tid >> 5;
    const int lane = tid & 31;
    const long long base = (long long)blockIdx.x * TE;

    // ---------------- gather: x[k][e], lane = edge (conflict-free transpose) ---------
    {
        const int e = lane;
        const long long ge = base + e;
        long long nidx = 0;
        if (ge < E) {
            nidx = (long long)((w < 4) ? eidx[ge] : eidx[E + ge]);
        }
        const int seg   = (w & 3) * 32;               // 32 source floats per warp
        const int xbase = (w < 4) ? seg : (H + seg);
        const float4* rp = reinterpret_cast<const float4*>(node + nidx * H + seg);
        #pragma unroll
        for (int m = 0; m < 8; m++) {
            float4 v = rp[m];
            const int k = xbase + m * 4;
            xs[(k + 0) * TE + e] = v.x;
            xs[(k + 1) * TE + e] = v.y;
            xs[(k + 2) * TE + e] = v.z;
            xs[(k + 3) * TE + e] = v.w;
        }
        if (w == 0) {
            float2 a = (ge < E) ? reinterpret_cast<const float2*>(attr)[ge]
                                : make_float2(0.f, 0.f);
            xs[256 * TE + e] = a.x;
            xs[257 * TE + e] = a.y;
        }
    }
    __syncthreads();

    // ---------------- layer 1: warp set = (w>>2) -> 16 edges; channels (w&3)*32+lane --
    const int c    = (w & 3) * 32 + lane;
    const int eoff = (w >> 2) * 16;                   // 0 or 16

    ull acc[8];
    #pragma unroll
    for (int p = 0; p < 8; p++) acc[p] = 0ull;

    const float* w1c = W1 + c;
    #pragma unroll 2
    for (int k = 0; k < IN; k++) {
        const float wv = w1c[k * H];
        const ull wp = pack2(wv, wv);
        const ulonglong2* xp = reinterpret_cast<const ulonglong2*>(&xs[k * TE + eoff]);
        ulonglong2 u0 = xp[0], u1 = xp[1], u2 = xp[2], u3 = xp[3];
        acc[0] = ffma2(wp, u0.x, acc[0]);
        acc[1] = ffma2(wp, u0.y, acc[1]);
        acc[2] = ffma2(wp, u1.x, acc[2]);
        acc[3] = ffma2(wp, u1.y, acc[3]);
        acc[4] = ffma2(wp, u2.x, acc[4]);
        acc[5] = ffma2(wp, u2.y, acc[5]);
        acc[6] = ffma2(wp, u3.x, acc[6]);
        acc[7] = ffma2(wp, u3.y, acc[7]);
    }

    // + b1 (before LN stats!)
    {
        const float bv = b1[c];
        const ull bp = pack2(bv, bv);
        #pragma unroll
        for (int p = 0; p < 8; p++) acc[p] = add2(acc[p], bp);
    }

    // ---------------- LN stats: butterfly over 32 lanes (32 channels per warp) -------
    {
        ull s[8], q[8];
        #pragma unroll
        for (int p = 0; p < 8; p++) { s[p] = acc[p]; q[p] = mul2(acc[p], acc[p]); }
        #pragma unroll
        for (int d = 16; d > 0; d >>= 1) {
            #pragma unroll
            for (int p = 0; p < 8; p++) {
                s[p] = add2(s[p], __shfl_xor_sync(0xFFFFFFFFu, s[p], d));
                q[p] = add2(q[p], __shfl_xor_sync(0xFFFFFFFFu, q[p], d));
            }
        }
        if (lane == 0) {
            #pragma unroll
            for (int p = 0; p < 8; p++) { psum[w][p] = s[p]; psq[w][p] = q[p]; }
        }
    }
    __syncthreads();

    // one warp finalizes mean/rstd for all 32 edges
    if (tid < TE) {
        const int e  = tid;
        const int st = e >> 4;           // edge set
        const int pi = (e & 15) >> 1;    // pair index
        const int sb = e & 1;
        float sum = 0.f, sq = 0.f;
        #pragma unroll
        for (int ww = 0; ww < 4; ww++) {
            float2 fs = unpack2(psum[st * 4 + ww][pi]);
            float2 fq = unpack2(psq[st * 4 + ww][pi]);
            sum += sb ? fs.y : fs.x;
            sq  += sb ? fq.y : fq.x;
        }
        const float mu  = sum * (1.0f / H);
        const float var = sq * (1.0f / H) - mu * mu;
        mu_s[e] = mu;
        rs_s[e] = rsqrtf(var + 1e-5f);
    }
    __syncthreads();

    // ---------------- normalize + relu, store h1s[k=c][e] (reuse xs, stride 34) ------
    float* h1s = xs;
    {
        const float g  = ln_g[c];
        const float bt = ln_b[c];
        #pragma unroll
        for (int p = 0; p < 8; p++) {
            float2 f = unpack2(acc[p]);
            const int e0 = eoff + 2 * p;
            float h0 = fmaxf((f.x - mu_s[e0])     * rs_s[e0]     * g + bt, 0.f);
            float h1 = fmaxf((f.y - mu_s[e0 + 1]) * rs_s[e0 + 1] * g + bt, 0.f);
            *reinterpret_cast<ull*>(&h1s[c * H1PAD + e0]) = pack2(h0, h1);
        }
    }
    __syncthreads();

    // ---------------- layer 2: warp -> channels (w&1)*32+lane, edges (w>>1)*8 --------
    const int c2    = (w & 1) * 32 + lane;
    const int eoff2 = (w >> 1) * 8;

    ull a2[4];
    #pragma unroll
    for (int p = 0; p < 4; p++) a2[p] = 0ull;

    const float* w2c = W2 + c2;
    #pragma unroll 2
    for (int k = 0; k < H; k++) {
        const float wv = w2c[k * H2];
        const ull wp = pack2(wv, wv);
        const ull* hp = reinterpret_cast<const ull*>(&h1s[k * H1PAD + eoff2]);
        a2[0] = ffma2(wp, hp[0], a2[0]);
        a2[1] = ffma2(wp, hp[1], a2[1]);
        a2[2] = ffma2(wp, hp[2], a2[2]);
        a2[3] = ffma2(wp, hp[3], a2[3]);
    }

    // ---------------- +b2, relu, *W3, reduce over 64 channels ------------------------
    {
        const float bv = b2[c2];
        const float wv = W3[c2];
        ull r[4];
        #pragma unroll
        for (int p = 0; p < 4; p++) {
            float2 f = unpack2(a2[p]);
            float h0 = fmaxf(f.x + bv, 0.f) * wv;
            float h1 = fmaxf(f.y + bv, 0.f) * wv;
            r[p] = pack2(h0, h1);
        }
        #pragma unroll
        for (int d = 16; d > 0; d >>= 1) {
            #pragma unroll
            for (int p = 0; p < 4; p++)
                r[p] = add2(r[p], __shfl_xor_sync(0xFFFFFFFFu, r[p], d));
        }
        if (lane == 0) {
            #pragma unroll
            for (int p = 0; p < 4; p++) l3p[w][p] = r[p];
        }
    }
    __syncthreads();

    if (tid < TE) {
        const int e   = tid;
        const long long ge = base + e;
        if (ge < E) {
            const int grp = e >> 3;
            const int pi  = (e & 7) >> 1;
            const int sb  = e & 1;
            float2 fa = unpack2(l3p[grp * 2][pi]);
            float2 fb = unpack2(l3p[grp * 2 + 1][pi]);
            const float v = (sb ? (fa.y + fb.y) : (fa.x + fb.x)) + b3[0];
            out[ge] = v;
        }
    }
}

extern "C" void kernel_launch(void* const* d_in, const int* in_sizes, int n_in,
                              void* d_out, int out_size)
{
    const float* node = (const float*)d_in[0];
    const int*   eidx = (const int*)d_in[1];      // int32 on device (harness dtype set)
    const float* attr = (const float*)d_in[2];
    const float* W1   = (const float*)d_in[3];
    const float* b1   = (const float*)d_in[4];
    const float* lng  = (const float*)d_in[5];
    const float* lnb  = (const float*)d_in[6];
    const float* W2   = (const float*)d_in[7];
    const float* b2   = (const float*)d_in[8];
    const float* W3   = (const float*)d_in[9];
    const float* b3   = (const float*)d_in[10];
    float* out = (float*)d_out;

    const long long E = (long long)in_sizes[1] / 2;   // edge_index is [2, E]
    const int tiles = (int)((E + TE - 1) / TE);

    edge_mlp_kernel<<<tiles, 256>>>(node, eidx, attr, W1, b1, lng, lnb,
                                    W2, b2, W3, b3, out, E);
}

// round 4
// speedup vs baseline: 1.3314x; 1.3314x over previous
#include <cuda_runtime.h>
#include <cuda_bf16.h>

// EdgeScoringMLP: out[e] = MLP(concat(node[i[e]], node[j[e]], attr[e]))
// H=128, IN=258, H2=64. fp32, channel-paired f32x2 register-tiled GEMM.
//
// Inputs (metadata order):
// 0 node_embed [N,128] f32 | 1 edge_index [2,E] i32 | 2 edge_attr [E,2] f32
// 3 W1 [258,128] | 4 b1[128] | 5 ln_gamma[128] | 6 ln_beta[128]
// 7 W2 [128,64]  | 8 b2[64]  | 9 W3[64,1] | 10 b3[1]   -> out [E] f32

typedef unsigned long long ull;

__device__ __forceinline__ ull pack2(float a, float b) {
    ull r; asm("mov.b64 %0, {%1, %2};" : "=l"(r) : "f"(a), "f"(b)); return r;
}
__device__ __forceinline__ float2 unpack2(ull v) {
    float2 r; asm("mov.b64 {%0, %1}, %2;" : "=f"(r.x), "=f"(r.y) : "l"(v)); return r;
}
__device__ __forceinline__ ull ffma2(ull a, ull b, ull c) {
    ull d; asm("fma.rn.f32x2 %0, %1, %2, %3;" : "=l"(d) : "l"(a), "l"(b), "l"(c)); return d;
}
__device__ __forceinline__ ull add2(ull a, ull b) {
    ull d; asm("add.rn.f32x2 %0, %1, %2;" : "=l"(d) : "l"(a), "l"(b)); return d;
}
__device__ __forceinline__ ull mul2(ull a, ull b) {
    ull d; asm("mul.rn.f32x2 %0, %1, %2;" : "=l"(d) : "l"(a), "l"(b)); return d;
}

static constexpr int H   = 128;
static constexpr int IN  = 2 * H + 2;   // 258
static constexpr int H2  = 64;
static constexpr int TE  = 32;          // edges per CTA
static constexpr int ST  = 36;          // xs row stride (floats), %4==0 for LDS.128 align

__global__ void __launch_bounds__(128)
edge_mlp_kernel(const float* __restrict__ node,
                const int* __restrict__ eidx,
                const float* __restrict__ attr,
                const float* __restrict__ W1,
                const float* __restrict__ b1,
                const float* __restrict__ ln_g,
                const float* __restrict__ ln_b,
                const float* __restrict__ W2,
                const float* __restrict__ b2,
                const float* __restrict__ W3,
                const float* __restrict__ b3,
                float* __restrict__ out,
                long long E)
{
    __shared__ __align__(16) float xs[IN * ST];   // 37.2 KB: x[k][e]; rows 0..127 reused as h1
    __shared__ int   sidx[64];
    __shared__ float lnp[4][32], lnq[4][32];
    __shared__ float mu_s[32], rs_s[32];
    __shared__ float l3p[2][32];

    const int tid  = threadIdx.x;
    const int w    = tid >> 5;
    const int lane = tid & 31;
    const int cg   = lane >> 3;          // 0..3  channel group (8 ch)
    const int eg   = lane & 7;           // 0..7  edge group (4 edges)
    const int E0   = eg * 4;
    const long long base = (long long)blockIdx.x * TE;

    // ------------------------- stage indices -------------------------------
    if (tid < 64) {
        const int  side = tid >> 5;
        const long long ge = base + (tid & 31);
        sidx[tid] = (ge < E) ? eidx[side * E + ge] : 0;
    }
    __syncthreads();

    // ------------------------- gather: xs[k][e] ----------------------------
    {
        const int r    = tid >> 1;       // 0..63  (side*32 + edge)
        const int half = tid & 1;        // which 64-float half of the node row
        const int side = r >> 5;
        const int e    = r & 31;
        const float4* np = reinterpret_cast<const float4*>(
            node + (size_t)sidx[r] * H + half * 64);
        const int kbase = side * H + half * 64;
        #pragma unroll
        for (int m = 0; m < 16; m++) {
            float4 v = np[m];
            const int k = kbase + m * 4;
            xs[(k + 0) * ST + e] = v.x;
            xs[(k + 1) * ST + e] = v.y;
            xs[(k + 2) * ST + e] = v.z;
            xs[(k + 3) * ST + e] = v.w;
        }
        if (tid < 32) {
            const long long ge = base + tid;
            float2 a = (ge < E) ? reinterpret_cast<const float2*>(attr)[ge]
                                : make_float2(0.f, 0.f);
            xs[256 * ST + tid] = a.x;
            xs[257 * ST + tid] = a.y;
        }
    }
    __syncthreads();

    // ------------------------- layer 1 -------------------------------------
    // warp w -> channels [w*32, w*32+32), thread -> 8 ch (4 pairs) x 4 edges
    const int C0 = w * 32 + cg * 8;

    ull acc[16];                          // acc[cp*4 + e]
    #pragma unroll
    for (int i = 0; i < 16; i++) acc[i] = 0ull;

    {
        const float* w1p = W1 + C0;
        #pragma unroll 4
        for (int k = 0; k < IN; k++) {
            float4 wa = *reinterpret_cast<const float4*>(w1p + (size_t)k * H);
            float4 wb = *reinterpret_cast<const float4*>(w1p + (size_t)k * H + 4);
            ull wp0 = reinterpret_cast<ull*>(&wa)[0];
            ull wp1 = reinterpret_cast<ull*>(&wa)[1];
            ull wp2 = reinterpret_cast<ull*>(&wb)[0];
            ull wp3 = reinterpret_cast<ull*>(&wb)[1];
            float4 xv = *reinterpret_cast<const float4*>(&xs[k * ST + E0]);
            ull xd0 = pack2(xv.x, xv.x);
            ull xd1 = pack2(xv.y, xv.y);
            ull xd2 = pack2(xv.z, xv.z);
            ull xd3 = pack2(xv.w, xv.w);
            acc[0]  = ffma2(wp0, xd0, acc[0]);
            acc[1]  = ffma2(wp0, xd1, acc[1]);
            acc[2]  = ffma2(wp0, xd2, acc[2]);
            acc[3]  = ffma2(wp0, xd3, acc[3]);
            acc[4]  = ffma2(wp1, xd0, acc[4]);
            acc[5]  = ffma2(wp1, xd1, acc[5]);
            acc[6]  = ffma2(wp1, xd2, acc[6]);
            acc[7]  = ffma2(wp1, xd3, acc[7]);
            acc[8]  = ffma2(wp2, xd0, acc[8]);
            acc[9]  = ffma2(wp2, xd1, acc[9]);
            acc[10] = ffma2(wp2, xd2, acc[10]);
            acc[11] = ffma2(wp2, xd3, acc[11]);
            acc[12] = ffma2(wp3, xd0, acc[12]);
            acc[13] = ffma2(wp3, xd1, acc[13]);
            acc[14] = ffma2(wp3, xd2, acc[14]);
            acc[15] = ffma2(wp3, xd3, acc[15]);
        }
    }

    // + b1
    {
        float4 ba = *reinterpret_cast<const float4*>(b1 + C0);
        float4 bb = *reinterpret_cast<const float4*>(b1 + C0 + 4);
        ull bp[4] = { reinterpret_cast<ull*>(&ba)[0], reinterpret_cast<ull*>(&ba)[1],
                      reinterpret_cast<ull*>(&bb)[0], reinterpret_cast<ull*>(&bb)[1] };
        #pragma unroll
        for (int cp = 0; cp < 4; cp++)
            #pragma unroll
            for (int e = 0; e < 4; e++)
                acc[cp * 4 + e] = add2(acc[cp * 4 + e], bp[cp]);
    }

    // ------------------------- LayerNorm stats -----------------------------
    {
        float s[4], q[4];
        #pragma unroll
        for (int e = 0; e < 4; e++) {
            ull t = add2(add2(acc[0 * 4 + e], acc[1 * 4 + e]),
                         add2(acc[2 * 4 + e], acc[3 * 4 + e]));
            float2 f = unpack2(t);
            s[e] = f.x + f.y;
            ull tq = add2(add2(mul2(acc[0 * 4 + e], acc[0 * 4 + e]),
                               mul2(acc[1 * 4 + e], acc[1 * 4 + e])),
                          add2(mul2(acc[2 * 4 + e], acc[2 * 4 + e]),
                               mul2(acc[3 * 4 + e], acc[3 * 4 + e])));
            float2 fq = unpack2(tq);
            q[e] = fq.x + fq.y;
        }
        #pragma unroll
        for (int d = 8; d <= 16; d <<= 1) {
            #pragma unroll
            for (int e = 0; e < 4; e++) {
                s[e] += __shfl_xor_sync(0xFFFFFFFFu, s[e], d);
                q[e] += __shfl_xor_sync(0xFFFFFFFFu, q[e], d);
            }
        }
        if (cg == 0) {
            #pragma unroll
            for (int e = 0; e < 4; e++) {
                lnp[w][E0 + e] = s[e];
                lnq[w][E0 + e] = q[e];
            }
        }
    }
    __syncthreads();

    if (tid < 32) {
        float sum = lnp[0][tid] + lnp[1][tid] + lnp[2][tid] + lnp[3][tid];
        float sq  = lnq[0][tid] + lnq[1][tid] + lnq[2][tid] + lnq[3][tid];
        const float mu  = sum * (1.0f / H);
        const float var = sq * (1.0f / H) - mu * mu;
        mu_s[tid] = mu;
        rs_s[tid] = rsqrtf(var + 1e-5f);
    }
    __syncthreads();

    // ------------------------- normalize + relu -> h1 in xs rows 0..127 ----
    {
        float g[8], bt[8];
        {
            float4 ga = *reinterpret_cast<const float4*>(ln_g + C0);
            float4 gb = *reinterpret_cast<const float4*>(ln_g + C0 + 4);
            float4 ba = *reinterpret_cast<const float4*>(ln_b + C0);
            float4 bb = *reinterpret_cast<const float4*>(ln_b + C0 + 4);
            g[0]=ga.x; g[1]=ga.y; g[2]=ga.z; g[3]=ga.w;
            g[4]=gb.x; g[5]=gb.y; g[6]=gb.z; g[7]=gb.w;
            bt[0]=ba.x; bt[1]=ba.y; bt[2]=ba.z; bt[3]=ba.w;
            bt[4]=bb.x; bt[5]=bb.y; bt[6]=bb.z; bt[7]=bb.w;
        }
        #pragma unroll
        for (int e = 0; e < 4; e++) {
            const float mue = mu_s[E0 + e];
            const float rse = rs_s[E0 + e];
            #pragma unroll
            for (int cp = 0; cp < 4; cp++) {
                float2 f = unpack2(acc[cp * 4 + e]);
                float h0 = fmaxf((f.x - mue) * rse * g[2 * cp]     + bt[2 * cp],     0.f);
                float h1 = fmaxf((f.y - mue) * rse * g[2 * cp + 1] + bt[2 * cp + 1], 0.f);
                xs[(C0 + 2 * cp)     * ST + E0 + e] = h0;
                xs[(C0 + 2 * cp + 1) * ST + E0 + e] = h1;
            }
        }
    }
    __syncthreads();

    // ------------------------- layer 2 -------------------------------------
    // warp -> cblk2 = w&1 (32 of 64 out ch), khalf = w>>1 (k 0..63 / 64..127)
    const int cblk2 = w & 1;
    const int khalf = w >> 1;
    const int C2 = cblk2 * 32 + cg * 8;
    const int k0 = khalf * 64;

    ull a2[16];
    #pragma unroll
    for (int i = 0; i < 16; i++) a2[i] = 0ull;

    {
        const float* w2p = W2 + C2;
        #pragma unroll 4
        for (int kk = 0; kk < 64; kk++) {
            const int k = k0 + kk;
            float4 wa = *reinterpret_cast<const float4*>(w2p + (size_t)k * H2);
            float4 wb = *reinterpret_cast<const float4*>(w2p + (size_t)k * H2 + 4);
            ull wp0 = reinterpret_cast<ull*>(&wa)[0];
            ull wp1 = reinterpret_cast<ull*>(&wa)[1];
            ull wp2 = reinterpret_cast<ull*>(&wb)[0];
            ull wp3 = reinterpret_cast<ull*>(&wb)[1];
            float4 xv = *reinterpret_cast<const float4*>(&xs[k * ST + E0]);
            ull xd0 = pack2(xv.x, xv.x);
            ull xd1 = pack2(xv.y, xv.y);
            ull xd2 = pack2(xv.z, xv.z);
            ull xd3 = pack2(xv.w, xv.w);
            a2[0]  = ffma2(wp0, xd0, a2[0]);
            a2[1]  = ffma2(wp0, xd1, a2[1]);
            a2[2]  = ffma2(wp0, xd2, a2[2]);
            a2[3]  = ffma2(wp0, xd3, a2[3]);
            a2[4]  = ffma2(wp1, xd0, a2[4]);
            a2[5]  = ffma2(wp1, xd1, a2[5]);
            a2[6]  = ffma2(wp1, xd2, a2[6]);
            a2[7]  = ffma2(wp1, xd3, a2[7]);
            a2[8]  = ffma2(wp2, xd0, a2[8]);
            a2[9]  = ffma2(wp2, xd1, a2[9]);
            a2[10] = ffma2(wp2, xd2, a2[10]);
            a2[11] = ffma2(wp2, xd3, a2[11]);
            a2[12] = ffma2(wp3, xd0, a2[12]);
            a2[13] = ffma2(wp3, xd1, a2[13]);
            a2[14] = ffma2(wp3, xd2, a2[14]);
            a2[15] = ffma2(wp3, xd3, a2[15]);
        }
    }
    __syncthreads();   // everyone done reading h1 (xs) before partial writes

    ull* part = reinterpret_cast<ull*>(xs);   // reuse xs region: 2*32*16 ull = 8KB
    if (w < 2) {
        #pragma unroll
        for (int i = 0; i < 16; i++) part[(w * 32 + lane) * 16 + i] = a2[i];
    }
    __syncthreads();

    if (w >= 2) {
        #pragma unroll
        for (int i = 0; i < 16; i++)
            a2[i] = add2(a2[i], part[((w - 2) * 32 + lane) * 16 + i]);

        float b2s[8], w3s[8];
        {
            float4 ba = *reinterpret_cast<const float4*>(b2 + C2);
            float4 bb = *reinterpret_cast<const float4*>(b2 + C2 + 4);
            float4 wa = *reinterpret_cast<const float4*>(W3 + C2);
            float4 wb = *reinterpret_cast<const float4*>(W3 + C2 + 4);
            b2s[0]=ba.x; b2s[1]=ba.y; b2s[2]=ba.z; b2s[3]=ba.w;
            b2s[4]=bb.x; b2s[5]=bb.y; b2s[6]=bb.z; b2s[7]=bb.w;
            w3s[0]=wa.x; w3s[1]=wa.y; w3s[2]=wa.z; w3s[3]=wa.w;
            w3s[4]=wb.x; w3s[5]=wb.y; w3s[6]=wb.z; w3s[7]=wb.w;
        }
        float r[4] = {0.f, 0.f, 0.f, 0.f};
        #pragma unroll
        for (int cp = 0; cp < 4; cp++) {
            #pragma unroll
            for (int e = 0; e < 4; e++) {
                float2 f = unpack2(a2[cp * 4 + e]);
                r[e] += fmaxf(f.x + b2s[2 * cp],     0.f) * w3s[2 * cp]
                      + fmaxf(f.y + b2s[2 * cp + 1], 0.f) * w3s[2 * cp + 1];
            }
        }
        #pragma unroll
        for (int d = 8; d <= 16; d <<= 1)
            #pragma unroll
            for (int e = 0; e < 4; e++)
                r[e] += __shfl_xor_sync(0xFFFFFFFFu, r[e], d);
        if (cg == 0) {
            #pragma unroll
            for (int e = 0; e < 4; e++) l3p[w - 2][E0 + e] = r[e];
        }
    }
    __syncthreads();

    if (tid < 32) {
        const long long ge = base + tid;
        if (ge < E) out[ge] = l3p[0][tid] + l3p[1][tid] + b3[0];
    }
}

extern "C" void kernel_launch(void* const* d_in, const int* in_sizes, int n_in,
                              void* d_out, int out_size)
{
    const float* node = (const float*)d_in[0];
    const int*   eidx = (const int*)d_in[1];
    const float* attr = (const float*)d_in[2];
    const float* W1   = (const float*)d_in[3];
    const float* b1   = (const float*)d_in[4];
    const float* lng  = (const float*)d_in[5];
    const float* lnb  = (const float*)d_in[6];
    const float* W2   = (const float*)d_in[7];
    const float* b2   = (const float*)d_in[8];
    const float* W3   = (const float*)d_in[9];
    const float* b3   = (const float*)d_in[10];
    float* out = (float*)d_out;

    const long long E = (long long)in_sizes[1] / 2;
    const int tiles = (int)((E + TE - 1) / TE);

    edge_mlp_kernel<<<tiles, 128>>>(node, eidx, attr, W1, b1, lng, lnb,
                                    W2, b2, W3, b3, out, E);
}